// round 2
// baseline (speedup 1.0000x reference)
#include <cuda_runtime.h>
#include <cstddef>

// ---------------- problem constants ----------------
#define B_   32
#define T_   128
#define P_   4
#define DIN_ 512
#define H_   512
#define C_   4096
#define NSPLIT 8
#define NB   128      // persistent grid: 1 block/SM, <= SM count
#define NT   256

// ---------------- device scratch (zero-init at load; reused across replays) ----------------
__device__ float g_xT  [(size_t)T_ * DIN_ * B_];   // [t][k][b]  8 MB
__device__ float g_mem [(size_t)T_ * B_ * C_];     // [t][b][c]  67 MB
__device__ float g_st  [(size_t)T_ * B_ * H_];     // [t][b][h]  8.4 MB
__device__ float g_a   [B_ * C_];                  // [b][c]
__device__ float g_pst [H_ * B_];                  // [k][b] pooled state for current step
__device__ float g_hpart[NSPLIT * B_ * H_];        // [(ks*B+b)*H + h]
__device__ unsigned g_bar_count;                   // returns to 0 every launch
__device__ volatile unsigned g_bar_sense;          // even #barriers -> returns to 0

// ---------------- f32x2 packed-math helpers (sm_103a) ----------------
__device__ __forceinline__ unsigned long long pack2(float a, float b) {
    unsigned long long d;
    unsigned x = __float_as_uint(a), y = __float_as_uint(b);
    asm("mov.b64 %0, {%1,%2};" : "=l"(d) : "r"(x), "r"(y));
    return d;
}
__device__ __forceinline__ unsigned long long dup2(float a) { return pack2(a, a); }
__device__ __forceinline__ void unpack2(unsigned long long s, float& a, float& b) {
    unsigned x, y;
    asm("mov.b64 {%0,%1}, %2;" : "=r"(x), "=r"(y) : "l"(s));
    a = __uint_as_float(x); b = __uint_as_float(y);
}
__device__ __forceinline__ unsigned long long fma2(unsigned long long a,
                                                   unsigned long long b,
                                                   unsigned long long c) {
    unsigned long long d;
    asm("fma.rn.f32x2 %0, %1, %2, %3;" : "=l"(d) : "l"(a), "l"(b), "l"(c));
    return d;
}
__device__ __forceinline__ float sigmoidf(float x) {
    return 1.0f / (1.0f + __expf(-x));
}

// ---------------- grid-wide software barrier (sense reversing) ----------------
__device__ __forceinline__ void grid_barrier(unsigned& sense) {
    __syncthreads();
    if (threadIdx.x == 0) {
        unsigned s = sense ^ 1u;
        sense = s;
        __threadfence();
        unsigned old = atomicAdd(&g_bar_count, 1u);
        if (old == (unsigned)(gridDim.x - 1)) {
            g_bar_count = 0;          // all arrived; none can re-arrive until release
            __threadfence();
            g_bar_sense = s;
        } else {
            while (g_bar_sense != s) { __nanosleep(32); }
        }
        __threadfence();
    }
    __syncthreads();
}

// =====================================================================
// Node 1: transpose x [B,T,DIN] -> g_xT [T,DIN,B]
// =====================================================================
__global__ void xT_kernel(const float* __restrict__ x) {
    int t = blockIdx.x;
    for (int e = threadIdx.x; e < DIN_ * B_; e += blockDim.x) {
        int k = e >> 5;
        int b = e & 31;
        g_xT[((size_t)t * DIN_ + k) * B_ + b] = x[((size_t)b * T_ + t) * DIN_ + k];
    }
}

// =====================================================================
// Node 2: persistent scan kernel. 128 blocks x 256 threads.
// Per step:
//   Phase A: g = [W_state | W_in] @ [pst | xT[t]]  (K=1024 fused GEMM),
//            gates + mem-pool epilogue -> g_mem[t], g_a
//   Phase B: split-K projection partials h = a @ W_proj^T
//   Phase C: reduce partials, clip -> g_st[t], out; pool pst for t+1
// =====================================================================
__global__ void __launch_bounds__(NT, 1) scan_kernel(
    const int*   __restrict__ prev_idx,
    const float* __restrict__ prev_w,
    const float* __restrict__ W_state,
    const float* __restrict__ W_in,
    const float* __restrict__ b_state,
    const float* __restrict__ W_proj,
    float* __restrict__ out)
{
    extern __shared__ __align__(16) float sm[];
    // Phase A layout:
    float* sA   = sm;                     // [1024][32]   128 KB  (k-major, b fast)
    float* sW   = sm + 1024 * 32;         // [16][128]    8 KB    (j = c_local*4 + gate)
    float* sw_  = sW + 16 * 128;          // [128] pooling weights
    int*   sidx = (int*)(sw_ + 128);      // [128] pooling indices

    const int tid = threadIdx.x;
    const int bid = blockIdx.x;
    unsigned sense = 0;

    for (int t = 0; t < T_; t++) {
        // ================= Phase A: fused gate GEMM =================
        {
            const int c0 = bid * 32;
            const int cl = tid & 31;     // c within tile
            const int bt = tid >> 5;     // warp id = batch quad (4 batches)

            // stage pooled state (skip at t=0: contribution is exactly 0)
            if (t > 0) {
                for (int i = tid; i < (H_ * B_) / 4; i += NT) {
                    ((float4*)sA)[i] = __ldcg((const float4*)g_pst + i);
                }
            }
            // stage x^T slice for step t
            {
                const float4* src = (const float4*)(g_xT + (size_t)t * DIN_ * B_);
                float4* dst = (float4*)(sA + 512 * 32);
                for (int i = tid; i < (DIN_ * B_) / 4; i += NT) dst[i] = src[i];
            }
            if (tid < 128) {
                int b = tid >> 2, p = tid & 3;
                sidx[tid] = prev_idx[(b * T_ + t) * P_ + p];
                sw_[tid]  = prev_w [(b * T_ + t) * P_ + p];
            }
            __syncthreads();

            unsigned long long acc[4][2];
#pragma unroll
            for (int g = 0; g < 4; g++) { acc[g][0] = 0ull; acc[g][1] = 0ull; }

            const int kstart = (t == 0) ? 512 : 0;
            for (int kk = kstart; kk < 1024; kk += 16) {
                // stage W chunk: sW[k][c_local*4 + gate]
                const float* Wsrc = (kk < 512) ? W_state : W_in;
                const int kof = (kk < 512) ? kk : kk - 512;
#pragma unroll
                for (int r = 0; r < 2; r++) {
                    int f  = tid + r * NT;            // 0..511
                    int jj = f >> 2;                  // 0..127
                    int kq = f & 3;                   // 0..3
                    int row = (jj & 3) * C_ + c0 + (jj >> 2);
                    float4 v = *(const float4*)&Wsrc[(size_t)row * 512 + kof + kq * 4];
                    sW[(kq * 4 + 0) * 128 + jj] = v.x;
                    sW[(kq * 4 + 1) * 128 + jj] = v.y;
                    sW[(kq * 4 + 2) * 128 + jj] = v.z;
                    sW[(kq * 4 + 3) * 128 + jj] = v.w;
                }
                __syncthreads();
#pragma unroll
                for (int k = 0; k < 16; k++) {
                    ulonglong2 av = *(const ulonglong2*)&sA[(kk + k) * 32 + bt * 4];
                    float4 w4 = *(const float4*)&sW[k * 128 + cl * 4];
                    unsigned long long pw;
                    pw = dup2(w4.x); acc[0][0] = fma2(pw, av.x, acc[0][0]); acc[0][1] = fma2(pw, av.y, acc[0][1]);
                    pw = dup2(w4.y); acc[1][0] = fma2(pw, av.x, acc[1][0]); acc[1][1] = fma2(pw, av.y, acc[1][1]);
                    pw = dup2(w4.z); acc[2][0] = fma2(pw, av.x, acc[2][0]); acc[2][1] = fma2(pw, av.y, acc[2][1]);
                    pw = dup2(w4.w); acc[3][0] = fma2(pw, av.x, acc[3][0]); acc[3][1] = fma2(pw, av.y, acc[3][1]);
                }
                __syncthreads();
            }

            // epilogue: gates + lattice mem pooling
            float ga[4][4];
#pragma unroll
            for (int g = 0; g < 4; g++) {
                unpack2(acc[g][0], ga[g][0], ga[g][1]);
                unpack2(acc[g][1], ga[g][2], ga[g][3]);
            }
            const int c = c0 + cl;
            const float bs0 = b_state[0 * C_ + c];
            const float bs1 = b_state[1 * C_ + c];
            const float bs2 = b_state[2 * C_ + c];
            const float bs3 = b_state[3 * C_ + c];
#pragma unroll
            for (int bb = 0; bb < 4; bb++) {
                const int b = bt * 4 + bb;
                float gi = ga[0][bb] + bs0;
                float gf = ga[1][bb] + bs1;
                float gm = ga[2][bb] + bs2;
                float go = ga[3][bb] + bs3;
                float pmem = 0.0f;
#pragma unroll
                for (int p = 0; p < P_; p++) {
                    int ip = sidx[b * 4 + p];
                    pmem += sw_[b * 4 + p] * __ldcg(&g_mem[((size_t)ip * B_ + b) * C_ + c]);
                }
                float ig = sigmoidf(gi);
                float fg = sigmoidf(gf);
                float mi = tanhf(gm);
                float og = sigmoidf(go);
                float mem = fminf(3.0f, fmaxf(-3.0f, ig * mi + fg * pmem));
                __stcg(&g_mem[((size_t)t * B_ + b) * C_ + c], mem);
                __stcg(&g_a[b * C_ + c], og * tanhf(mem));
            }
        }
        grid_barrier(sense);

        // ================= Phase B: split-K projection partials =================
        {
            float* s_pa = sm;             // [16][32]
            float* s_pw = sm + 16 * 32;   // [16][32]
            const int ht = bid >> 3;      // 0..15
            const int ks = bid & 7;       // 0..7
            const int h0 = ht * 32;
            const int kb = ks * 512;
            const int hl = tid & 31;
            const int bt = tid >> 5;

            unsigned long long a0 = 0ull, a1 = 0ull;
            for (int kk = 0; kk < 512; kk += 16) {
#pragma unroll
                for (int r = 0; r < 2; r++) {
                    int f = tid + r * NT;    // 0..511
                    int row = f >> 4;        // 0..31
                    int k = f & 15;
                    s_pa[k * 32 + row] = __ldcg(&g_a[row * C_ + kb + kk + k]);
                    s_pw[k * 32 + row] = W_proj[(size_t)(h0 + row) * C_ + kb + kk + k];
                }
                __syncthreads();
#pragma unroll
                for (int k = 0; k < 16; k++) {
                    float w = s_pw[k * 32 + hl];
                    ulonglong2 av = *(const ulonglong2*)&s_pa[k * 32 + bt * 4];
                    unsigned long long pw = dup2(w);
                    a0 = fma2(pw, av.x, a0);
                    a1 = fma2(pw, av.y, a1);
                }
                __syncthreads();
            }
            float h0v, h1v, h2v, h3v;
            unpack2(a0, h0v, h1v);
            unpack2(a1, h2v, h3v);
            const int b = bt * 4;
            __stcg(&g_hpart[(ks * B_ + b + 0) * H_ + h0 + hl], h0v);
            __stcg(&g_hpart[(ks * B_ + b + 1) * H_ + h0 + hl], h1v);
            __stcg(&g_hpart[(ks * B_ + b + 2) * H_ + h0 + hl], h2v);
            __stcg(&g_hpart[(ks * B_ + b + 3) * H_ + h0 + hl], h3v);
        }
        grid_barrier(sense);

        // ================= Phase C: finalize + next-step pooling =================
        if (tid < 128) {
            int e = bid * 128 + tid;      // 0..16383
            int b = e >> 9;
            int h = e & 511;
            float s = 0.0f;
#pragma unroll
            for (int ks = 0; ks < NSPLIT; ks++)
                s += __ldcg(&g_hpart[(ks * B_ + b) * H_ + h]);
            s = fminf(3.0f, fmaxf(-3.0f, s));
            out[((size_t)b * T_ + t) * H_ + h] = s;
            __stcg(&g_st[((size_t)t * B_ + b) * H_ + h], s);
            if (t < T_ - 1) {
                float acc = 0.0f;
#pragma unroll
                for (int p = 0; p < P_; p++) {
                    int ip = prev_idx[(b * T_ + (t + 1)) * P_ + p];
                    float wv = prev_w[(b * T_ + (t + 1)) * P_ + p];
                    float v = (ip == t) ? s : __ldcg(&g_st[((size_t)ip * B_ + b) * H_ + h]);
                    acc += wv * v;
                }
                __stcg(&g_pst[h * B_ + b], acc);
            }
        }
        grid_barrier(sense);
    }
}

// =====================================================================
// launch
// =====================================================================
extern "C" void kernel_launch(void* const* d_in, const int* in_sizes, int n_in,
                              void* d_out, int out_size) {
    const float* x        = (const float*)d_in[0];
    const int*   prev_idx = (const int*)  d_in[1];
    const float* prev_w   = (const float*)d_in[2];
    const float* W_in     = (const float*)d_in[3];
    const float* W_state  = (const float*)d_in[4];
    const float* b_state  = (const float*)d_in[5];
    const float* W_proj   = (const float*)d_in[6];
    float* out = (float*)d_out;
    (void)in_sizes; (void)n_in; (void)out_size;

    const int smem = (1024 * 32 + 16 * 128 + 128 + 128) * (int)sizeof(float);
    static int configured = 0;
    cudaFuncSetAttribute(scan_kernel, cudaFuncAttributeMaxDynamicSharedMemorySize, smem);
    (void)configured;

    xT_kernel<<<T_, 256>>>(x);
    scan_kernel<<<NB, NT, smem>>>(prev_idx, prev_w, W_state, W_in, b_state, W_proj, out);
}

// round 3
// speedup vs baseline: 1.4320x; 1.4320x over previous
#include <cuda_runtime.h>
#include <cstddef>

// ---------------- problem constants ----------------
#define B_   32
#define T_   128
#define P_   4
#define DIN_ 512
#define H_   512
#define C_   4096
#define G_   16384
#define NB   128
#define NT   512

// ---------------- device scratch ----------------
__device__ float g_pi [(size_t)B_ * T_ * G_];   // [b*T+t][j]        268 MB
__device__ float g_mem[(size_t)T_ * C_ * B_];   // [t][c][b]          67 MB
__device__ float g_st [(size_t)T_ * H_ * B_];   // [t][h][b]         8.4 MB
__device__ float g_a  [C_ * B_];                // [c][b]
__device__ float g_pst[H_ * B_];                // [k][b]
__device__ unsigned g_bar_count;
__device__ volatile unsigned g_bar_sense;

// ---------------- f32x2 helpers ----------------
__device__ __forceinline__ unsigned long long pack2(float a, float b) {
    unsigned long long d;
    unsigned x = __float_as_uint(a), y = __float_as_uint(b);
    asm("mov.b64 %0, {%1,%2};" : "=l"(d) : "r"(x), "r"(y));
    return d;
}
__device__ __forceinline__ unsigned long long dup2(float a) { return pack2(a, a); }
__device__ __forceinline__ void unpack2(unsigned long long s, float& a, float& b) {
    unsigned x, y;
    asm("mov.b64 {%0,%1}, %2;" : "=r"(x), "=r"(y) : "l"(s));
    a = __uint_as_float(x); b = __uint_as_float(y);
}
__device__ __forceinline__ unsigned long long fma2(unsigned long long a,
                                                   unsigned long long b,
                                                   unsigned long long c) {
    unsigned long long d;
    asm("fma.rn.f32x2 %0, %1, %2, %3;" : "=l"(d) : "l"(a), "l"(b), "l"(c));
    return d;
}
__device__ __forceinline__ float sigmoidf(float x) { return 1.0f / (1.0f + __expf(-x)); }

// ---------------- grid barrier ----------------
__device__ __forceinline__ void grid_barrier(unsigned& sense) {
    __syncthreads();
    if (threadIdx.x == 0) {
        unsigned s = sense ^ 1u;
        sense = s;
        __threadfence();
        unsigned old = atomicAdd(&g_bar_count, 1u);
        if (old == (unsigned)(gridDim.x - 1)) {
            g_bar_count = 0;
            __threadfence();
            g_bar_sense = s;
        } else {
            while (g_bar_sense != s) { __nanosleep(32); }
        }
        __threadfence();
    }
    __syncthreads();
}

// =====================================================================
// Kernel 1: proj_in = x @ W_in^T  -> g_pi[(b*T+t)*G + j]
// =====================================================================
__global__ void __launch_bounds__(256) proj_in_kernel(const float* __restrict__ x,
                                                      const float* __restrict__ W_in) {
    __shared__ __align__(16) float As[16][128];
    __shared__ __align__(16) float Bs[16][128];

    const int tid = threadIdx.x;
    const int m0 = blockIdx.y * 128;
    const int n0 = blockIdx.x * 128;
    const int tm = tid >> 4;
    const int tn = tid & 15;

    unsigned long long acc[8][4];
#pragma unroll
    for (int i = 0; i < 8; i++)
#pragma unroll
        for (int j = 0; j < 4; j++) acc[i][j] = 0ull;

    for (int kk = 0; kk < DIN_; kk += 16) {
#pragma unroll
        for (int r = 0; r < 2; r++) {
            int f = tid + r * 256;
            int row = f >> 2;
            int kq = f & 3;
            float4 va = *(const float4*)&x[(size_t)(m0 + row) * DIN_ + kk + kq * 4];
            As[kq * 4 + 0][row] = va.x; As[kq * 4 + 1][row] = va.y;
            As[kq * 4 + 2][row] = va.z; As[kq * 4 + 3][row] = va.w;
            float4 vb = *(const float4*)&W_in[(size_t)(n0 + row) * DIN_ + kk + kq * 4];
            Bs[kq * 4 + 0][row] = vb.x; Bs[kq * 4 + 1][row] = vb.y;
            Bs[kq * 4 + 2][row] = vb.z; Bs[kq * 4 + 3][row] = vb.w;
        }
        __syncthreads();
#pragma unroll
        for (int k = 0; k < 16; k++) {
            float4 a0 = *(const float4*)&As[k][tm * 8];
            float4 a1 = *(const float4*)&As[k][tm * 8 + 4];
            ulonglong2 b0 = *(const ulonglong2*)&Bs[k][tn * 8];
            ulonglong2 b1 = *(const ulonglong2*)&Bs[k][tn * 8 + 4];
            float av[8] = {a0.x, a0.y, a0.z, a0.w, a1.x, a1.y, a1.z, a1.w};
#pragma unroll
            for (int i = 0; i < 8; i++) {
                unsigned long long pa = dup2(av[i]);
                acc[i][0] = fma2(pa, b0.x, acc[i][0]);
                acc[i][1] = fma2(pa, b0.y, acc[i][1]);
                acc[i][2] = fma2(pa, b1.x, acc[i][2]);
                acc[i][3] = fma2(pa, b1.y, acc[i][3]);
            }
        }
        __syncthreads();
    }
#pragma unroll
    for (int i = 0; i < 8; i++) {
        float o[8];
        unpack2(acc[i][0], o[0], o[1]); unpack2(acc[i][1], o[2], o[3]);
        unpack2(acc[i][2], o[4], o[5]); unpack2(acc[i][3], o[6], o[7]);
        size_t base = (size_t)(m0 + tm * 8 + i) * G_ + n0 + tn * 8;
        *(float4*)&g_pi[base]     = make_float4(o[0], o[1], o[2], o[3]);
        *(float4*)&g_pi[base + 4] = make_float4(o[4], o[5], o[6], o[7]);
    }
}

// =====================================================================
// Kernel 2: persistent scan. 128 blocks x 512 threads, lane = batch.
// =====================================================================
__global__ void __launch_bounds__(NT, 1) scan_kernel(
    const int*   __restrict__ prev_idx,
    const float* __restrict__ prev_w,
    const float* __restrict__ W_state,
    const float* __restrict__ b_state,
    const float* __restrict__ W_proj,
    float* __restrict__ out)
{
    extern __shared__ __align__(16) float sm[];
    float*  sWp   = sm;                       // [c][h0..3]    16384 f (persistent)
    float*  s_pst = sm + 16384;               // [k][b]        16384 f (alias s_a)
    float2* sW2   = (float2*)(sm + 32768);    // [kp][j]        8192 f
    float*  part  = sm + 32768;               // alias (B reduce) 2048 f

    const int tid = threadIdx.x;
    const int bid = blockIdx.x;
    const int w   = tid >> 5;   // warp 0..15
    const int b   = tid & 31;   // lane = batch
    unsigned sense = 0;

    // ---- stage W_proj rows [bid*4 .. bid*4+3] once, layout sWp[c*4+h] ----
    {
        const int h0 = bid * 4;
        for (int e = tid; e < 4 * C_; e += NT) {
            int h = e >> 12;
            int c = e & (C_ - 1);
            sWp[c * 4 + h] = __ldg(&W_proj[(size_t)(h0 + h) * C_ + c]);
        }
    }

    // per-thread constants (c-tile: c = bid*32 + 2w + ci)
    const int cA0 = bid * 32 + 2 * w;
    float bst[2][4];
#pragma unroll
    for (int ci = 0; ci < 2; ci++)
#pragma unroll
        for (int g = 0; g < 4; g++)
            bst[ci][g] = __ldg(&b_state[g * C_ + cA0 + ci]);

    for (int t = 0; t < T_; t++) {
        // ================= Phase A =================
        int   idxA[P_];
        float wA[P_];
#pragma unroll
        for (int p = 0; p < P_; p++) {
            idxA[p] = __ldg(&prev_idx[(b * T_ + t) * P_ + p]);
            wA[p]   = __ldg(&prev_w [(b * T_ + t) * P_ + p]);
        }
        float piv[2][4], pmv[2][P_];
#pragma unroll
        for (int ci = 0; ci < 2; ci++) {
            const int c = cA0 + ci;
#pragma unroll
            for (int g = 0; g < 4; g++)
                piv[ci][g] = __ldg(&g_pi[(size_t)(b * T_ + t) * G_ + g * C_ + c]);
#pragma unroll
            for (int p = 0; p < P_; p++)
                pmv[ci][p] = g_mem[((size_t)idxA[p] * C_ + c) * B_ + b];
        }

        unsigned long long acc[8];
#pragma unroll
        for (int i = 0; i < 8; i++) acc[i] = 0ull;

        if (t > 0) {
            // stage pooled state [k][b]
            for (int i = tid; i < (H_ * B_) / 4; i += NT)
                ((float4*)s_pst)[i] = __ldcg(((const float4*)g_pst) + i);

            for (int kk = 0; kk < H_; kk += 64) {
                // stage W_state chunk: sW2[kp*128 + j], j = c_l*4 + g
#pragma unroll
                for (int i = 0; i < 4; i++) {
                    int e = tid + i * NT;           // 0..2047
                    int j = e & 127;
                    int q = e >> 7;                 // 0..15
                    int jglob = (j & 3) * C_ + bid * 32 + (j >> 2);
                    float4 v = __ldg((const float4*)&W_state[(size_t)jglob * H_ + kk + q * 4]);
                    sW2[(q * 2    ) * 128 + j] = make_float2(v.x, v.y);
                    sW2[(q * 2 + 1) * 128 + j] = make_float2(v.z, v.w);
                }
                __syncthreads();
#pragma unroll
                for (int kp = 0; kp < 32; kp++) {
                    const int k = kk + 2 * kp;
                    unsigned long long pa = pack2(s_pst[k * 32 + b], s_pst[(k + 1) * 32 + b]);
                    const ulonglong2* wp = (const ulonglong2*)&sW2[kp * 128 + w * 8];
                    ulonglong2 q0 = wp[0], q1 = wp[1], q2 = wp[2], q3 = wp[3];
                    acc[0] = fma2(q0.x, pa, acc[0]); acc[1] = fma2(q0.y, pa, acc[1]);
                    acc[2] = fma2(q1.x, pa, acc[2]); acc[3] = fma2(q1.y, pa, acc[3]);
                    acc[4] = fma2(q2.x, pa, acc[4]); acc[5] = fma2(q2.y, pa, acc[5]);
                    acc[6] = fma2(q3.x, pa, acc[6]); acc[7] = fma2(q3.y, pa, acc[7]);
                }
                __syncthreads();
            }
        }

        // epilogue: gates + mem update + a
#pragma unroll
        for (int ci = 0; ci < 2; ci++) {
            const int c = cA0 + ci;
            float pmem = 0.f;
#pragma unroll
            for (int p = 0; p < P_; p++) pmem += wA[p] * pmv[ci][p];
            float gv[4];
#pragma unroll
            for (int g = 0; g < 4; g++) {
                float lo, hi;
                unpack2(acc[4 * ci + g], lo, hi);
                gv[g] = lo + hi + piv[ci][g] + bst[ci][g];
            }
            float ig = sigmoidf(gv[0]);
            float fg = sigmoidf(gv[1]);
            float mi = tanhf(gv[2]);
            float og = sigmoidf(gv[3]);
            float mem = fminf(3.f, fmaxf(-3.f, ig * mi + fg * pmem));
            g_mem[((size_t)t * C_ + c) * B_ + b] = mem;
            __stcg(&g_a[c * B_ + b], og * tanhf(mem));
        }
        grid_barrier(sense);

        // ================= Phase B: projection (4 h rows, full K) =================
        unsigned long long pacc0 = 0ull, pacc1 = 0ull;
        float* s_a = s_pst;
        for (int ch = 0; ch < 8; ch++) {
            const int cc = ch * 512;
            for (int i = tid; i < (512 * 32) / 4; i += NT)
                ((float4*)s_a)[i] = __ldcg((const float4*)g_a + ch * 4096 + i);
            __syncthreads();
#pragma unroll
            for (int k = 0; k < 32; k++) {
                const int cl = w * 32 + k;
                unsigned long long pa = dup2(s_a[cl * 32 + b]);
                ulonglong2 q = *(const ulonglong2*)&sWp[(cc + cl) * 4];
                pacc0 = fma2(q.x, pa, pacc0);
                pacc1 = fma2(q.y, pa, pacc1);
            }
            __syncthreads();
        }
        {
            float v0, v1, v2, v3;
            unpack2(pacc0, v0, v1);
            unpack2(pacc1, v2, v3);
            part[(w * 4 + 0) * 32 + b] = v0;
            part[(w * 4 + 1) * 32 + b] = v1;
            part[(w * 4 + 2) * 32 + b] = v2;
            part[(w * 4 + 3) * 32 + b] = v3;
        }
        __syncthreads();
        if (tid < 128) {
            const int hl = tid >> 5;
            const int bb = tid & 31;
            float s = 0.f;
#pragma unroll
            for (int ww = 0; ww < 16; ww++) s += part[(ww * 4 + hl) * 32 + bb];
            s = fminf(3.f, fmaxf(-3.f, s));
            const int hg = bid * 4 + hl;
            g_st[((size_t)t * H_ + hg) * B_ + bb] = s;
            out[((size_t)bb * T_ + t) * H_ + hg] = s;
            if (t < T_ - 1) {
                float pstv = 0.f;
#pragma unroll
                for (int p = 0; p < P_; p++) {
                    int ip   = __ldg(&prev_idx[(bb * T_ + t + 1) * P_ + p]);
                    float wv = __ldg(&prev_w [(bb * T_ + t + 1) * P_ + p]);
                    float v  = (ip == t) ? s : g_st[((size_t)ip * H_ + hg) * B_ + bb];
                    pstv += wv * v;
                }
                __stcg(&g_pst[hg * B_ + bb], pstv);
            }
        }
        grid_barrier(sense);
    }
}

// =====================================================================
// launch
// =====================================================================
extern "C" void kernel_launch(void* const* d_in, const int* in_sizes, int n_in,
                              void* d_out, int out_size) {
    const float* x        = (const float*)d_in[0];
    const int*   prev_idx = (const int*)  d_in[1];
    const float* prev_w   = (const float*)d_in[2];
    const float* W_in     = (const float*)d_in[3];
    const float* W_state  = (const float*)d_in[4];
    const float* b_state  = (const float*)d_in[5];
    const float* W_proj   = (const float*)d_in[6];
    float* out = (float*)d_out;
    (void)in_sizes; (void)n_in; (void)out_size;

    const int smem = (16384 + 16384 + 8192) * (int)sizeof(float);   // 160 KB
    cudaFuncSetAttribute(scan_kernel, cudaFuncAttributeMaxDynamicSharedMemorySize, smem);

    proj_in_kernel<<<dim3(G_ / 128, (B_ * T_) / 128), 256>>>(x, W_in);
    scan_kernel<<<NB, NT, smem>>>(prev_idx, prev_w, W_state, b_state, W_proj, out);
}

// round 4
// speedup vs baseline: 1.4322x; 1.0002x over previous
#include <cuda_runtime.h>
#include <cstddef>

// ---------------- problem constants ----------------
#define B_   32
#define T_   128
#define P_   4
#define DIN_ 512
#define H_   512
#define C_   4096
#define G_   16384
#define NB   128
#define NT   512

// ---------------- device scratch ----------------
__device__ float g_pi [(size_t)B_ * T_ * G_];   // [b*T+t][j]        268 MB
__device__ float g_mem[(size_t)T_ * C_ * B_];   // [t][c][b]          67 MB
__device__ float g_st [(size_t)T_ * H_ * B_];   // [t][h][b]         8.4 MB
__device__ float g_a  [C_ * B_];                // [c][b]
__device__ float g_pst[H_ * B_];                // [k][b]
__device__ unsigned g_bar_count;
__device__ volatile unsigned g_bar_sense;

// ---------------- f32x2 helpers ----------------
__device__ __forceinline__ unsigned long long pack2(float a, float b) {
    unsigned long long d;
    unsigned x = __float_as_uint(a), y = __float_as_uint(b);
    asm("mov.b64 %0, {%1,%2};" : "=l"(d) : "r"(x), "r"(y));
    return d;
}
__device__ __forceinline__ unsigned long long dup2(float a) { return pack2(a, a); }
__device__ __forceinline__ void unpack2(unsigned long long s, float& a, float& b) {
    unsigned x, y;
    asm("mov.b64 {%0,%1}, %2;" : "=r"(x), "=r"(y) : "l"(s));
    a = __uint_as_float(x); b = __uint_as_float(y);
}
__device__ __forceinline__ unsigned long long fma2(unsigned long long a,
                                                   unsigned long long b,
                                                   unsigned long long c) {
    unsigned long long d;
    asm("fma.rn.f32x2 %0, %1, %2, %3;" : "=l"(d) : "l"(a), "l"(b), "l"(c));
    return d;
}
__device__ __forceinline__ float sigmoidf(float x) { return 1.0f / (1.0f + __expf(-x)); }

// ---------------- grid barrier ----------------
__device__ __forceinline__ void grid_barrier(unsigned& sense) {
    __syncthreads();
    if (threadIdx.x == 0) {
        unsigned s = sense ^ 1u;
        sense = s;
        __threadfence();
        unsigned old = atomicAdd(&g_bar_count, 1u);
        if (old == (unsigned)(gridDim.x - 1)) {
            g_bar_count = 0;
            __threadfence();
            g_bar_sense = s;
        } else {
            while (g_bar_sense != s) { __nanosleep(32); }
        }
        __threadfence();
    }
    __syncthreads();
}

// =====================================================================
// Kernel 1: proj_in = x @ W_in^T  -> g_pi[(b*T+t)*G + j]
// =====================================================================
__global__ void __launch_bounds__(256) proj_in_kernel(const float* __restrict__ x,
                                                      const float* __restrict__ W_in) {
    __shared__ __align__(16) float As[16][128];
    __shared__ __align__(16) float Bs[16][128];

    const int tid = threadIdx.x;
    const int m0 = blockIdx.y * 128;
    const int n0 = blockIdx.x * 128;
    const int tm = tid >> 4;
    const int tn = tid & 15;

    unsigned long long acc[8][4];
#pragma unroll
    for (int i = 0; i < 8; i++)
#pragma unroll
        for (int j = 0; j < 4; j++) acc[i][j] = 0ull;

    for (int kk = 0; kk < DIN_; kk += 16) {
#pragma unroll
        for (int r = 0; r < 2; r++) {
            int f = tid + r * 256;
            int row = f >> 2;
            int kq = f & 3;
            float4 va = *(const float4*)&x[(size_t)(m0 + row) * DIN_ + kk + kq * 4];
            As[kq * 4 + 0][row] = va.x; As[kq * 4 + 1][row] = va.y;
            As[kq * 4 + 2][row] = va.z; As[kq * 4 + 3][row] = va.w;
            float4 vb = *(const float4*)&W_in[(size_t)(n0 + row) * DIN_ + kk + kq * 4];
            Bs[kq * 4 + 0][row] = vb.x; Bs[kq * 4 + 1][row] = vb.y;
            Bs[kq * 4 + 2][row] = vb.z; Bs[kq * 4 + 3][row] = vb.w;
        }
        __syncthreads();
#pragma unroll
        for (int k = 0; k < 16; k++) {
            float4 a0 = *(const float4*)&As[k][tm * 8];
            float4 a1 = *(const float4*)&As[k][tm * 8 + 4];
            ulonglong2 b0 = *(const ulonglong2*)&Bs[k][tn * 8];
            ulonglong2 b1 = *(const ulonglong2*)&Bs[k][tn * 8 + 4];
            float av[8] = {a0.x, a0.y, a0.z, a0.w, a1.x, a1.y, a1.z, a1.w};
#pragma unroll
            for (int i = 0; i < 8; i++) {
                unsigned long long pa = dup2(av[i]);
                acc[i][0] = fma2(pa, b0.x, acc[i][0]);
                acc[i][1] = fma2(pa, b0.y, acc[i][1]);
                acc[i][2] = fma2(pa, b1.x, acc[i][2]);
                acc[i][3] = fma2(pa, b1.y, acc[i][3]);
            }
        }
        __syncthreads();
    }
#pragma unroll
    for (int i = 0; i < 8; i++) {
        float o[8];
        unpack2(acc[i][0], o[0], o[1]); unpack2(acc[i][1], o[2], o[3]);
        unpack2(acc[i][2], o[4], o[5]); unpack2(acc[i][3], o[6], o[7]);
        size_t base = (size_t)(m0 + tm * 8 + i) * G_ + n0 + tn * 8;
        *(float4*)&g_pi[base]     = make_float4(o[0], o[1], o[2], o[3]);
        *(float4*)&g_pi[base + 4] = make_float4(o[4], o[5], o[6], o[7]);
    }
}

// =====================================================================
// Kernel 2: persistent scan. 128 blocks x 512 threads, lane = batch.
// =====================================================================
__global__ void __launch_bounds__(NT, 1) scan_kernel(
    const int*   __restrict__ prev_idx,
    const float* __restrict__ prev_w,
    const float* __restrict__ W_state,
    const float* __restrict__ b_state,
    const float* __restrict__ W_proj,
    float* __restrict__ out)
{
    extern __shared__ __align__(16) float sm[];
    float*  sWp   = sm;                       // [c][h0..3]    16384 f (persistent)
    float*  s_pst = sm + 16384;               // [k][b]        16384 f (alias s_a)
    float2* sW2   = (float2*)(sm + 32768);    // [kp][j]        8192 f
    float*  part  = sm + 32768;               // alias (B reduce) 2048 f

    const int tid = threadIdx.x;
    const int bid = blockIdx.x;
    const int w   = tid >> 5;   // warp 0..15
    const int b   = tid & 31;   // lane = batch
    unsigned sense = 0;

    // ---- stage W_proj rows [bid*4 .. bid*4+3] once, layout sWp[c*4+h] ----
    {
        const int h0 = bid * 4;
        for (int e = tid; e < 4 * C_; e += NT) {
            int h = e >> 12;
            int c = e & (C_ - 1);
            sWp[c * 4 + h] = __ldg(&W_proj[(size_t)(h0 + h) * C_ + c]);
        }
    }

    // per-thread constants (c-tile: c = bid*32 + 2w + ci)
    const int cA0 = bid * 32 + 2 * w;
    float bst[2][4];
#pragma unroll
    for (int ci = 0; ci < 2; ci++)
#pragma unroll
        for (int g = 0; g < 4; g++)
            bst[ci][g] = __ldg(&b_state[g * C_ + cA0 + ci]);

    for (int t = 0; t < T_; t++) {
        // ================= Phase A =================
        int   idxA[P_];
        float wA[P_];
#pragma unroll
        for (int p = 0; p < P_; p++) {
            idxA[p] = __ldg(&prev_idx[(b * T_ + t) * P_ + p]);
            wA[p]   = __ldg(&prev_w [(b * T_ + t) * P_ + p]);
        }
        float piv[2][4], pmv[2][P_];
#pragma unroll
        for (int ci = 0; ci < 2; ci++) {
            const int c = cA0 + ci;
#pragma unroll
            for (int g = 0; g < 4; g++)
                piv[ci][g] = __ldg(&g_pi[(size_t)(b * T_ + t) * G_ + g * C_ + c]);
#pragma unroll
            for (int p = 0; p < P_; p++)
                pmv[ci][p] = g_mem[((size_t)idxA[p] * C_ + c) * B_ + b];
        }

        unsigned long long acc[8];
#pragma unroll
        for (int i = 0; i < 8; i++) acc[i] = 0ull;

        if (t > 0) {
            // stage pooled state [k][b]
            for (int i = tid; i < (H_ * B_) / 4; i += NT)
                ((float4*)s_pst)[i] = __ldcg(((const float4*)g_pst) + i);

            for (int kk = 0; kk < H_; kk += 64) {
                // stage W_state chunk: sW2[kp*128 + j], j = c_l*4 + g
#pragma unroll
                for (int i = 0; i < 4; i++) {
                    int e = tid + i * NT;           // 0..2047
                    int j = e & 127;
                    int q = e >> 7;                 // 0..15
                    int jglob = (j & 3) * C_ + bid * 32 + (j >> 2);
                    float4 v = __ldg((const float4*)&W_state[(size_t)jglob * H_ + kk + q * 4]);
                    sW2[(q * 2    ) * 128 + j] = make_float2(v.x, v.y);
                    sW2[(q * 2 + 1) * 128 + j] = make_float2(v.z, v.w);
                }
                __syncthreads();
#pragma unroll
                for (int kp = 0; kp < 32; kp++) {
                    const int k = kk + 2 * kp;
                    unsigned long long pa = pack2(s_pst[k * 32 + b], s_pst[(k + 1) * 32 + b]);
                    const ulonglong2* wp = (const ulonglong2*)&sW2[kp * 128 + w * 8];
                    ulonglong2 q0 = wp[0], q1 = wp[1], q2 = wp[2], q3 = wp[3];
                    acc[0] = fma2(q0.x, pa, acc[0]); acc[1] = fma2(q0.y, pa, acc[1]);
                    acc[2] = fma2(q1.x, pa, acc[2]); acc[3] = fma2(q1.y, pa, acc[3]);
                    acc[4] = fma2(q2.x, pa, acc[4]); acc[5] = fma2(q2.y, pa, acc[5]);
                    acc[6] = fma2(q3.x, pa, acc[6]); acc[7] = fma2(q3.y, pa, acc[7]);
                }
                __syncthreads();
            }
        }

        // epilogue: gates + mem update + a
#pragma unroll
        for (int ci = 0; ci < 2; ci++) {
            const int c = cA0 + ci;
            float pmem = 0.f;
#pragma unroll
            for (int p = 0; p < P_; p++) pmem += wA[p] * pmv[ci][p];
            float gv[4];
#pragma unroll
            for (int g = 0; g < 4; g++) {
                float lo, hi;
                unpack2(acc[4 * ci + g], lo, hi);
                gv[g] = lo + hi + piv[ci][g] + bst[ci][g];
            }
            float ig = sigmoidf(gv[0]);
            float fg = sigmoidf(gv[1]);
            float mi = tanhf(gv[2]);
            float og = sigmoidf(gv[3]);
            float mem = fminf(3.f, fmaxf(-3.f, ig * mi + fg * pmem));
            g_mem[((size_t)t * C_ + c) * B_ + b] = mem;
            __stcg(&g_a[c * B_ + b], og * tanhf(mem));
        }
        grid_barrier(sense);

        // ================= Phase B: projection (4 h rows, full K) =================
        unsigned long long pacc0 = 0ull, pacc1 = 0ull;
        float* s_a = s_pst;
        for (int ch = 0; ch < 8; ch++) {
            const int cc = ch * 512;
            for (int i = tid; i < (512 * 32) / 4; i += NT)
                ((float4*)s_a)[i] = __ldcg((const float4*)g_a + ch * 4096 + i);
            __syncthreads();
#pragma unroll
            for (int k = 0; k < 32; k++) {
                const int cl = w * 32 + k;
                unsigned long long pa = dup2(s_a[cl * 32 + b]);
                ulonglong2 q = *(const ulonglong2*)&sWp[(cc + cl) * 4];
                pacc0 = fma2(q.x, pa, pacc0);
                pacc1 = fma2(q.y, pa, pacc1);
            }
            __syncthreads();
        }
        {
            float v0, v1, v2, v3;
            unpack2(pacc0, v0, v1);
            unpack2(pacc1, v2, v3);
            part[(w * 4 + 0) * 32 + b] = v0;
            part[(w * 4 + 1) * 32 + b] = v1;
            part[(w * 4 + 2) * 32 + b] = v2;
            part[(w * 4 + 3) * 32 + b] = v3;
        }
        __syncthreads();
        if (tid < 128) {
            const int hl = tid >> 5;
            const int bb = tid & 31;
            float s = 0.f;
#pragma unroll
            for (int ww = 0; ww < 16; ww++) s += part[(ww * 4 + hl) * 32 + bb];
            s = fminf(3.f, fmaxf(-3.f, s));
            const int hg = bid * 4 + hl;
            g_st[((size_t)t * H_ + hg) * B_ + bb] = s;
            out[((size_t)bb * T_ + t) * H_ + hg] = s;
            if (t < T_ - 1) {
                float pstv = 0.f;
#pragma unroll
                for (int p = 0; p < P_; p++) {
                    int ip   = __ldg(&prev_idx[(bb * T_ + t + 1) * P_ + p]);
                    float wv = __ldg(&prev_w [(bb * T_ + t + 1) * P_ + p]);
                    float v  = (ip == t) ? s : g_st[((size_t)ip * H_ + hg) * B_ + bb];
                    pstv += wv * v;
                }
                __stcg(&g_pst[hg * B_ + bb], pstv);
            }
        }
        grid_barrier(sense);
    }
}

// =====================================================================
// launch
// =====================================================================
extern "C" void kernel_launch(void* const* d_in, const int* in_sizes, int n_in,
                              void* d_out, int out_size) {
    const float* x        = (const float*)d_in[0];
    const int*   prev_idx = (const int*)  d_in[1];
    const float* prev_w   = (const float*)d_in[2];
    const float* W_in     = (const float*)d_in[3];
    const float* W_state  = (const float*)d_in[4];
    const float* b_state  = (const float*)d_in[5];
    const float* W_proj   = (const float*)d_in[6];
    float* out = (float*)d_out;
    (void)in_sizes; (void)n_in; (void)out_size;

    const int smem = (16384 + 16384 + 8192) * (int)sizeof(float);   // 160 KB
    cudaFuncSetAttribute(scan_kernel, cudaFuncAttributeMaxDynamicSharedMemorySize, smem);

    proj_in_kernel<<<dim3(G_ / 128, (B_ * T_) / 128), 256>>>(x, W_in);
    scan_kernel<<<NB, NT, smem>>>(prev_idx, prev_w, W_state, b_state, W_proj, out);
}

// round 5
// speedup vs baseline: 1.4332x; 1.0006x over previous
#include <cuda_runtime.h>
#include <cstddef>

// ---------------- problem constants ----------------
#define B_   32
#define T_   128
#define P_   4
#define DIN_ 512
#define H_   512
#define C_   4096
#define G_   16384
#define NB   128
#define NT   512

// ---------------- device scratch ----------------
__device__ float g_pi [(size_t)B_ * T_ * G_];   // [b*T+t][j]        268 MB
__device__ float g_mem[(size_t)T_ * C_ * B_];   // [t][c][b]          67 MB
__device__ float g_st [(size_t)T_ * H_ * B_];   // [t][h][b]         8.4 MB
__device__ float g_a  [C_ * B_];                // [c][b]
__device__ float g_pst[H_ * B_];                // [k][b]
__device__ unsigned g_bar_count;
__device__ volatile unsigned g_bar_sense;

// ---------------- f32x2 helpers ----------------
__device__ __forceinline__ unsigned long long pack2(float a, float b) {
    unsigned long long d;
    unsigned x = __float_as_uint(a), y = __float_as_uint(b);
    asm("mov.b64 %0, {%1,%2};" : "=l"(d) : "r"(x), "r"(y));
    return d;
}
__device__ __forceinline__ unsigned long long dup2(float a) { return pack2(a, a); }
__device__ __forceinline__ void unpack2(unsigned long long s, float& a, float& b) {
    unsigned x, y;
    asm("mov.b64 {%0,%1}, %2;" : "=r"(x), "=r"(y) : "l"(s));
    a = __uint_as_float(x); b = __uint_as_float(y);
}
__device__ __forceinline__ unsigned long long fma2(unsigned long long a,
                                                   unsigned long long b,
                                                   unsigned long long c) {
    unsigned long long d;
    asm("fma.rn.f32x2 %0, %1, %2, %3;" : "=l"(d) : "l"(a), "l"(b), "l"(c));
    return d;
}
__device__ __forceinline__ float sigmoidf(float x) { return 1.0f / (1.0f + __expf(-x)); }

// ---------------- grid barrier ----------------
__device__ __forceinline__ void grid_barrier(unsigned& sense) {
    __syncthreads();
    if (threadIdx.x == 0) {
        unsigned s = sense ^ 1u;
        sense = s;
        __threadfence();
        unsigned old = atomicAdd(&g_bar_count, 1u);
        if (old == (unsigned)(gridDim.x - 1)) {
            g_bar_count = 0;
            __threadfence();
            g_bar_sense = s;
        } else {
            while (g_bar_sense != s) { __nanosleep(32); }
        }
        __threadfence();
    }
    __syncthreads();
}

// =====================================================================
// Kernel 1: proj_in = x @ W_in^T  -> g_pi[(b*T+t)*G + j]
// =====================================================================
__global__ void __launch_bounds__(256) proj_in_kernel(const float* __restrict__ x,
                                                      const float* __restrict__ W_in) {
    __shared__ __align__(16) float As[16][128];
    __shared__ __align__(16) float Bs[16][128];

    const int tid = threadIdx.x;
    const int m0 = blockIdx.y * 128;
    const int n0 = blockIdx.x * 128;
    const int tm = tid >> 4;
    const int tn = tid & 15;

    unsigned long long acc[8][4];
#pragma unroll
    for (int i = 0; i < 8; i++)
#pragma unroll
        for (int j = 0; j < 4; j++) acc[i][j] = 0ull;

    for (int kk = 0; kk < DIN_; kk += 16) {
#pragma unroll
        for (int r = 0; r < 2; r++) {
            int f = tid + r * 256;
            int row = f >> 2;
            int kq = f & 3;
            float4 va = *(const float4*)&x[(size_t)(m0 + row) * DIN_ + kk + kq * 4];
            As[kq * 4 + 0][row] = va.x; As[kq * 4 + 1][row] = va.y;
            As[kq * 4 + 2][row] = va.z; As[kq * 4 + 3][row] = va.w;
            float4 vb = *(const float4*)&W_in[(size_t)(n0 + row) * DIN_ + kk + kq * 4];
            Bs[kq * 4 + 0][row] = vb.x; Bs[kq * 4 + 1][row] = vb.y;
            Bs[kq * 4 + 2][row] = vb.z; Bs[kq * 4 + 3][row] = vb.w;
        }
        __syncthreads();
#pragma unroll
        for (int k = 0; k < 16; k++) {
            float4 a0 = *(const float4*)&As[k][tm * 8];
            float4 a1 = *(const float4*)&As[k][tm * 8 + 4];
            ulonglong2 b0 = *(const ulonglong2*)&Bs[k][tn * 8];
            ulonglong2 b1 = *(const ulonglong2*)&Bs[k][tn * 8 + 4];
            float av[8] = {a0.x, a0.y, a0.z, a0.w, a1.x, a1.y, a1.z, a1.w};
#pragma unroll
            for (int i = 0; i < 8; i++) {
                unsigned long long pa = dup2(av[i]);
                acc[i][0] = fma2(pa, b0.x, acc[i][0]);
                acc[i][1] = fma2(pa, b0.y, acc[i][1]);
                acc[i][2] = fma2(pa, b1.x, acc[i][2]);
                acc[i][3] = fma2(pa, b1.y, acc[i][3]);
            }
        }
        __syncthreads();
    }
#pragma unroll
    for (int i = 0; i < 8; i++) {
        float o[8];
        unpack2(acc[i][0], o[0], o[1]); unpack2(acc[i][1], o[2], o[3]);
        unpack2(acc[i][2], o[4], o[5]); unpack2(acc[i][3], o[6], o[7]);
        size_t base = (size_t)(m0 + tm * 8 + i) * G_ + n0 + tn * 8;
        *(float4*)&g_pi[base]     = make_float4(o[0], o[1], o[2], o[3]);
        *(float4*)&g_pi[base + 4] = make_float4(o[4], o[5], o[6], o[7]);
    }
}

// =====================================================================
// Kernel 2: persistent scan. 128 blocks x 512 threads, lane = batch.
// =====================================================================
__global__ void __launch_bounds__(NT, 1) scan_kernel(
    const int*   __restrict__ prev_idx,
    const float* __restrict__ prev_w,
    const float* __restrict__ W_state,
    const float* __restrict__ b_state,
    const float* __restrict__ W_proj,
    float* __restrict__ out)
{
    extern __shared__ __align__(16) float sm[];
    float*  sWp   = sm;                       // [c][h0..3]    16384 f (persistent)
    float*  s_pst = sm + 16384;               // [k][b]        16384 f (alias s_a)
    float2* sW2   = (float2*)(sm + 32768);    // [kp][j]        8192 f
    float*  part  = sm + 32768;               // alias (B reduce) 2048 f

    const int tid = threadIdx.x;
    const int bid = blockIdx.x;
    const int w   = tid >> 5;   // warp 0..15
    const int b   = tid & 31;   // lane = batch
    unsigned sense = 0;

    // ---- stage W_proj rows [bid*4 .. bid*4+3] once, layout sWp[c*4+h] ----
    {
        const int h0 = bid * 4;
        for (int e = tid; e < 4 * C_; e += NT) {
            int h = e >> 12;
            int c = e & (C_ - 1);
            sWp[c * 4 + h] = __ldg(&W_proj[(size_t)(h0 + h) * C_ + c]);
        }
    }

    // per-thread constants (c-tile: c = bid*32 + 2w + ci)
    const int cA0 = bid * 32 + 2 * w;
    float bst[2][4];
#pragma unroll
    for (int ci = 0; ci < 2; ci++)
#pragma unroll
        for (int g = 0; g < 4; g++)
            bst[ci][g] = __ldg(&b_state[g * C_ + cA0 + ci]);

    for (int t = 0; t < T_; t++) {
        // ================= Phase A =================
        int   idxA[P_];
        float wA[P_];
#pragma unroll
        for (int p = 0; p < P_; p++) {
            idxA[p] = __ldg(&prev_idx[(b * T_ + t) * P_ + p]);
            wA[p]   = __ldg(&prev_w [(b * T_ + t) * P_ + p]);
        }
        float piv[2][4], pmv[2][P_];
#pragma unroll
        for (int ci = 0; ci < 2; ci++) {
            const int c = cA0 + ci;
#pragma unroll
            for (int g = 0; g < 4; g++)
                piv[ci][g] = __ldg(&g_pi[(size_t)(b * T_ + t) * G_ + g * C_ + c]);
#pragma unroll
            for (int p = 0; p < P_; p++)
                pmv[ci][p] = g_mem[((size_t)idxA[p] * C_ + c) * B_ + b];
        }

        unsigned long long acc[8];
#pragma unroll
        for (int i = 0; i < 8; i++) acc[i] = 0ull;

        if (t > 0) {
            // stage pooled state [k][b]
            for (int i = tid; i < (H_ * B_) / 4; i += NT)
                ((float4*)s_pst)[i] = __ldcg(((const float4*)g_pst) + i);

            for (int kk = 0; kk < H_; kk += 64) {
                // stage W_state chunk: sW2[kp*128 + j], j = c_l*4 + g
#pragma unroll
                for (int i = 0; i < 4; i++) {
                    int e = tid + i * NT;           // 0..2047
                    int j = e & 127;
                    int q = e >> 7;                 // 0..15
                    int jglob = (j & 3) * C_ + bid * 32 + (j >> 2);
                    float4 v = __ldg((const float4*)&W_state[(size_t)jglob * H_ + kk + q * 4]);
                    sW2[(q * 2    ) * 128 + j] = make_float2(v.x, v.y);
                    sW2[(q * 2 + 1) * 128 + j] = make_float2(v.z, v.w);
                }
                __syncthreads();
#pragma unroll
                for (int kp = 0; kp < 32; kp++) {
                    const int k = kk + 2 * kp;
                    unsigned long long pa = pack2(s_pst[k * 32 + b], s_pst[(k + 1) * 32 + b]);
                    const ulonglong2* wp = (const ulonglong2*)&sW2[kp * 128 + w * 8];
                    ulonglong2 q0 = wp[0], q1 = wp[1], q2 = wp[2], q3 = wp[3];
                    acc[0] = fma2(q0.x, pa, acc[0]); acc[1] = fma2(q0.y, pa, acc[1]);
                    acc[2] = fma2(q1.x, pa, acc[2]); acc[3] = fma2(q1.y, pa, acc[3]);
                    acc[4] = fma2(q2.x, pa, acc[4]); acc[5] = fma2(q2.y, pa, acc[5]);
                    acc[6] = fma2(q3.x, pa, acc[6]); acc[7] = fma2(q3.y, pa, acc[7]);
                }
                __syncthreads();
            }
        }

        // epilogue: gates + mem update + a
#pragma unroll
        for (int ci = 0; ci < 2; ci++) {
            const int c = cA0 + ci;
            float pmem = 0.f;
#pragma unroll
            for (int p = 0; p < P_; p++) pmem += wA[p] * pmv[ci][p];
            float gv[4];
#pragma unroll
            for (int g = 0; g < 4; g++) {
                float lo, hi;
                unpack2(acc[4 * ci + g], lo, hi);
                gv[g] = lo + hi + piv[ci][g] + bst[ci][g];
            }
            float ig = sigmoidf(gv[0]);
            float fg = sigmoidf(gv[1]);
            float mi = tanhf(gv[2]);
            float og = sigmoidf(gv[3]);
            float mem = fminf(3.f, fmaxf(-3.f, ig * mi + fg * pmem));
            g_mem[((size_t)t * C_ + c) * B_ + b] = mem;
            __stcg(&g_a[c * B_ + b], og * tanhf(mem));
        }
        grid_barrier(sense);

        // ================= Phase B: projection (4 h rows, full K) =================
        unsigned long long pacc0 = 0ull, pacc1 = 0ull;
        float* s_a = s_pst;
        for (int ch = 0; ch < 8; ch++) {
            const int cc = ch * 512;
            for (int i = tid; i < (512 * 32) / 4; i += NT)
                ((float4*)s_a)[i] = __ldcg((const float4*)g_a + ch * 4096 + i);
            __syncthreads();
#pragma unroll
            for (int k = 0; k < 32; k++) {
                const int cl = w * 32 + k;
                unsigned long long pa = dup2(s_a[cl * 32 + b]);
                ulonglong2 q = *(const ulonglong2*)&sWp[(cc + cl) * 4];
                pacc0 = fma2(q.x, pa, pacc0);
                pacc1 = fma2(q.y, pa, pacc1);
            }
            __syncthreads();
        }
        {
            float v0, v1, v2, v3;
            unpack2(pacc0, v0, v1);
            unpack2(pacc1, v2, v3);
            part[(w * 4 + 0) * 32 + b] = v0;
            part[(w * 4 + 1) * 32 + b] = v1;
            part[(w * 4 + 2) * 32 + b] = v2;
            part[(w * 4 + 3) * 32 + b] = v3;
        }
        __syncthreads();
        if (tid < 128) {
            const int hl = tid >> 5;
            const int bb = tid & 31;
            float s = 0.f;
#pragma unroll
            for (int ww = 0; ww < 16; ww++) s += part[(ww * 4 + hl) * 32 + bb];
            s = fminf(3.f, fmaxf(-3.f, s));
            const int hg = bid * 4 + hl;
            g_st[((size_t)t * H_ + hg) * B_ + bb] = s;
            out[((size_t)bb * T_ + t) * H_ + hg] = s;
            if (t < T_ - 1) {
                float pstv = 0.f;
#pragma unroll
                for (int p = 0; p < P_; p++) {
                    int ip   = __ldg(&prev_idx[(bb * T_ + t + 1) * P_ + p]);
                    float wv = __ldg(&prev_w [(bb * T_ + t + 1) * P_ + p]);
                    float v  = (ip == t) ? s : g_st[((size_t)ip * H_ + hg) * B_ + bb];
                    pstv += wv * v;
                }
                __stcg(&g_pst[hg * B_ + bb], pstv);
            }
        }
        grid_barrier(sense);
    }
}

// =====================================================================
// launch
// =====================================================================
extern "C" void kernel_launch(void* const* d_in, const int* in_sizes, int n_in,
                              void* d_out, int out_size) {
    const float* x        = (const float*)d_in[0];
    const int*   prev_idx = (const int*)  d_in[1];
    const float* prev_w   = (const float*)d_in[2];
    const float* W_in     = (const float*)d_in[3];
    const float* W_state  = (const float*)d_in[4];
    const float* b_state  = (const float*)d_in[5];
    const float* W_proj   = (const float*)d_in[6];
    float* out = (float*)d_out;
    (void)in_sizes; (void)n_in; (void)out_size;

    const int smem = (16384 + 16384 + 8192) * (int)sizeof(float);   // 160 KB
    cudaFuncSetAttribute(scan_kernel, cudaFuncAttributeMaxDynamicSharedMemorySize, smem);

    proj_in_kernel<<<dim3(G_ / 128, (B_ * T_) / 128), 256>>>(x, W_in);
    scan_kernel<<<NB, NT, smem>>>(prev_idx, prev_w, W_state, b_state, W_proj, out);
}